// round 16
// baseline (speedup 1.0000x reference)
#include <cuda_runtime.h>
#include <cuda_bf16.h>
#include <math.h>

#define B_   4096
#define M_   65536
#define D_   64
#define CD_  32
#define S_   64
#define MCHUNK (M_/S_)        // 1024 slots per CTA
#define MT    128             // slots per staged tile (2 x 64 compute halves)
#define NTILES (MCHUNK/MT)    // 8
#define BT    256             // batch rows per CTA (8 warps x 32 rows)
#define NTHREADS 256

// smem buffer layout (byte offsets within one buffer); all tiles 1024-aligned
#define oKH   0u
#define oKL   16384u
#define oVH   32768u
#define oVL   49152u
#define oCH   65536u
#define oCL   81920u
#define oBias 98304u          // 128 floats
#define BUFSZ 99328u          // padded to 1024
#define SMEM_TOTAL (2u*BUFSZ)

// ---------------- device scratch (no cudaMalloc allowed) -------------------
__device__ __nv_bfloat16 g_kh[(size_t)M_*D_],  g_kl[(size_t)M_*D_];
__device__ __nv_bfloat16 g_vh[(size_t)M_*D_],  g_vl[(size_t)M_*D_];
__device__ __nv_bfloat16 g_ch[(size_t)M_*CD_], g_cl[(size_t)M_*CD_];
__device__ float g_bias[M_];
__device__ float g_pout[(size_t)B_*S_*D_];
__device__ float g_pden[(size_t)B_*S_];

// ---------------- helpers ---------------------------------------------------
__device__ __forceinline__ unsigned smem_u32(const void* p) {
    unsigned a;
    asm("{ .reg .u64 t; cvta.to.shared.u64 t, %1; cvt.u32.u64 %0, t; }"
        : "=r"(a) : "l"(p));
    return a;
}
__device__ __forceinline__ unsigned swz(unsigned o) { return o ^ ((o >> 3) & 0x70); }

__device__ __forceinline__ void cp16(unsigned d, const void* s) {
    asm volatile("cp.async.cg.shared.global [%0], [%1], 16;" :: "r"(d), "l"(s));
}
#define CP_COMMIT() asm volatile("cp.async.commit_group;" ::: "memory")
#define CP_WAIT0()  asm volatile("cp.async.wait_group 0;" ::: "memory")

__device__ __forceinline__ void ldsm_x4(unsigned* r, unsigned a) {
    asm volatile("ldmatrix.sync.aligned.m8n8.x4.shared.b16 {%0,%1,%2,%3}, [%4];"
        : "=r"(r[0]), "=r"(r[1]), "=r"(r[2]), "=r"(r[3]) : "r"(a));
}
__device__ __forceinline__ void ldsm_x4_t(unsigned* r, unsigned a) {
    asm volatile("ldmatrix.sync.aligned.m8n8.x4.trans.shared.b16 {%0,%1,%2,%3}, [%4];"
        : "=r"(r[0]), "=r"(r[1]), "=r"(r[2]), "=r"(r[3]) : "r"(a));
}

// D(16x8,f32) += A(16x16,bf16) * B(16x8,bf16)
__device__ __forceinline__ void mma16816(float* c, const unsigned* a, const unsigned* b) {
    asm volatile("mma.sync.aligned.m16n8k16.row.col.f32.bf16.bf16.f32 "
        "{%0,%1,%2,%3}, {%4,%5,%6,%7}, {%8,%9}, {%0,%1,%2,%3};"
        : "+f"(c[0]), "+f"(c[1]), "+f"(c[2]), "+f"(c[3])
        : "r"(a[0]), "r"(a[1]), "r"(a[2]), "r"(a[3]), "r"(b[0]), "r"(b[1]));
}

// pack (a=low half, b=high half) to bf16x2 hi word + bf16x2 residual word
__device__ __forceinline__ void pack_hl(float a, float b, unsigned& h, unsigned& l) {
    asm("cvt.rn.bf16x2.f32 %0, %1, %2;" : "=r"(h) : "f"(b), "f"(a));
    float ha = __uint_as_float(h << 16);
    float hb = __uint_as_float(h & 0xffff0000u);
    asm("cvt.rn.bf16x2.f32 %0, %1, %2;" : "=r"(l) : "f"(b - hb), "f"(a - ha));
}

// ---------------- prep: hi/lo splits + bias (4 elems/thread, vectorized) ----
__global__ void prep_kernel(const float* __restrict__ mk,
                            const float* __restrict__ mv,
                            const float* __restrict__ mc,
                            const float* __restrict__ ts,
                            const int* __restrict__ used) {
    size_t i = (size_t)blockIdx.x * 256 + threadIdx.x;   // group of 4 elems
    if (i < (size_t)M_ * D_ / 4) {
        float4 x = ((const float4*)mk)[i];
        unsigned h0, l0, h1, l1;
        pack_hl(x.x, x.y, h0, l0); pack_hl(x.z, x.w, h1, l1);
        ((uint2*)g_kh)[i] = make_uint2(h0, h1);
        ((uint2*)g_kl)[i] = make_uint2(l0, l1);
        float4 y = ((const float4*)mv)[i];
        pack_hl(y.x, y.y, h0, l0); pack_hl(y.z, y.w, h1, l1);
        ((uint2*)g_vh)[i] = make_uint2(h0, h1);
        ((uint2*)g_vl)[i] = make_uint2(l0, l1);
    }
    if (i < (size_t)M_ * CD_ / 4) {
        float4 x = ((const float4*)mc)[i];
        unsigned h0, l0, h1, l1;
        pack_hl(x.x, x.y, h0, l0); pack_hl(x.z, x.w, h1, l1);
        ((uint2*)g_ch)[i] = make_uint2(h0, h1);
        ((uint2*)g_cl)[i] = make_uint2(l0, l1);
    }
    if (i < M_) {
        float b = -1e9f;
        if (used[i] != 0) b = 0.3f * expf(-0.1f * (1.0f - ts[i]));
        g_bias[i] = b;
    }
}

// ---------------- tile stage (cp.async, fixed-trip, shift-only math) --------
__device__ __forceinline__ void stage_tile(int m0, unsigned dst, int tid) {
#pragma unroll
    for (int i = 0; i < 8; i++) {      // K hi/lo: 2048 cp16
        int idx = tid + i * 256;
        int t = idx >> 10, r = (idx >> 3) & 127, c = idx & 7;
        const char* src = (const char*)((t ? g_kl : g_kh) + ((size_t)(m0 + r) << 6) + c * 8);
        cp16(dst + (t ? oKL : oKH) + swz((unsigned)(r * 128 + c * 16)), src);
    }
#pragma unroll
    for (int i = 0; i < 8; i++) {      // V hi/lo: 2048 cp16
        int idx = tid + i * 256;
        int t = idx >> 10, r = (idx >> 3) & 127, c = idx & 7;
        const char* src = (const char*)((t ? g_vl : g_vh) + ((size_t)(m0 + r) << 6) + c * 8);
        cp16(dst + (t ? oVL : oVH) + swz((unsigned)(r * 128 + c * 16)), src);
    }
#pragma unroll
    for (int i = 0; i < 4; i++) {      // C hi/lo: 1024 cp16 (64B payload/row)
        int idx = tid + i * 256;
        int t = idx >> 9, r = (idx >> 2) & 127, c = idx & 3;
        const char* src = (const char*)((t ? g_cl : g_ch) + ((size_t)(m0 + r) << 5) + c * 8);
        cp16(dst + (t ? oCL : oCH) + swz((unsigned)(r * 128 + c * 16)), src);
    }
    if (tid < 32)                      // bias: 128 floats
        cp16(dst + oBias + (unsigned)(tid * 16), (const char*)(g_bias + m0 + tid * 4));
    CP_COMMIT();
}

// ---------------- per-half building blocks (forceinlined) -------------------
// B fragments shared across BOTH M-blocks of this warp: 8 MMAs per hi-ldsm.
__device__ __forceinline__ void qk_half2(float sacc0[8][4], float sacc1[8][4],
                                         const unsigned qh[2][4][4], const unsigned ql[2][4][4],
                                         const unsigned ch[2][2][4], const unsigned cl[2][2][4],
                                         unsigned buf, unsigned hoff,
                                         const float* sB, int tq,
                                         unsigned kbase0, unsigned kbase1) {
#pragma unroll
    for (int n = 0; n < 8; n++) {
        float2 b = *(const float2*)(sB + n * 8 + 2 * tq);
        sacc0[n][0] = b.x; sacc0[n][1] = b.y; sacc0[n][2] = b.x; sacc0[n][3] = b.y;
        sacc1[n][0] = b.x; sacc1[n][1] = b.y; sacc1[n][2] = b.x; sacc1[n][3] = b.y;
    }
    // K-hi: feeds qh AND ql of BOTH m-blocks (8 MMAs/ldsm)
#pragma unroll
    for (int kbp = 0; kbp < 2; kbp++) {
        const unsigned a0 = buf + oKH + hoff + (kbp ? kbase1 : kbase0);
#pragma unroll
        for (int n = 0; n < 8; n++) {
            unsigned bfr[4];
            ldsm_x4(bfr, a0 + (unsigned)(n * 1024));
            mma16816(sacc0[n], qh[0][2 * kbp],     bfr);
            mma16816(sacc0[n], qh[0][2 * kbp + 1], bfr + 2);
            mma16816(sacc1[n], qh[1][2 * kbp],     bfr);
            mma16816(sacc1[n], qh[1][2 * kbp + 1], bfr + 2);
            mma16816(sacc0[n], ql[0][2 * kbp],     bfr);
            mma16816(sacc0[n], ql[0][2 * kbp + 1], bfr + 2);
            mma16816(sacc1[n], ql[1][2 * kbp],     bfr);
            mma16816(sacc1[n], ql[1][2 * kbp + 1], bfr + 2);
        }
    }
    // K-lo: feeds qh of both m-blocks (4 MMAs/ldsm)
#pragma unroll
    for (int kbp = 0; kbp < 2; kbp++) {
        const unsigned a0 = buf + oKL + hoff + (kbp ? kbase1 : kbase0);
#pragma unroll
        for (int n = 0; n < 8; n++) {
            unsigned bfr[4];
            ldsm_x4(bfr, a0 + (unsigned)(n * 1024));
            mma16816(sacc0[n], qh[0][2 * kbp],     bfr);
            mma16816(sacc0[n], qh[0][2 * kbp + 1], bfr + 2);
            mma16816(sacc1[n], qh[1][2 * kbp],     bfr);
            mma16816(sacc1[n], qh[1][2 * kbp + 1], bfr + 2);
        }
    }
    // C-hi: ch and cl of both m-blocks (8 MMAs/ldsm)
    {
        const unsigned a0 = buf + oCH + hoff + kbase0;
#pragma unroll
        for (int n = 0; n < 8; n++) {
            unsigned bfr[4];
            ldsm_x4(bfr, a0 + (unsigned)(n * 1024));
            mma16816(sacc0[n], ch[0][0], bfr);
            mma16816(sacc0[n], ch[0][1], bfr + 2);
            mma16816(sacc1[n], ch[1][0], bfr);
            mma16816(sacc1[n], ch[1][1], bfr + 2);
            mma16816(sacc0[n], cl[0][0], bfr);
            mma16816(sacc0[n], cl[0][1], bfr + 2);
            mma16816(sacc1[n], cl[1][0], bfr);
            mma16816(sacc1[n], cl[1][1], bfr + 2);
        }
    }
    // C-lo: ch of both m-blocks (4 MMAs/ldsm)
    {
        const unsigned a0 = buf + oCL + hoff + kbase0;
#pragma unroll
        for (int n = 0; n < 8; n++) {
            unsigned bfr[4];
            ldsm_x4(bfr, a0 + (unsigned)(n * 1024));
            mma16816(sacc0[n], ch[0][0], bfr);
            mma16816(sacc0[n], ch[0][1], bfr + 2);
            mma16816(sacc1[n], ch[1][0], bfr);
            mma16816(sacc1[n], ch[1][1], bfr + 2);
        }
    }
}

__device__ __forceinline__ void epi_half(const float sacc[8][4],
                                         unsigned phi[4][4], unsigned plo[4][4],
                                         float& dden0, float& dden1) {
#pragma unroll
    for (int n = 0; n < 8; n++) {
        float p0 = __expf(sacc[n][0]);
        float p1 = __expf(sacc[n][1]);
        float p2 = __expf(sacc[n][2]);
        float p3 = __expf(sacc[n][3]);
        dden0 += p0 + p1;
        dden1 += p2 + p3;
        int kb = n >> 1, e = (n & 1) * 2;
        pack_hl(p0, p1, phi[kb][e],     plo[kb][e]);
        pack_hl(p2, p3, phi[kb][e + 1], plo[kb][e + 1]);
    }
}

// PV for both m-blocks: V fragments shared (8 MMAs per hi-ldsm, 4 per lo)
__device__ __forceinline__ void pv_half2(float oacc0[8][4], float oacc1[8][4],
                                         const unsigned phi0[4][4], const unsigned plo0[4][4],
                                         const unsigned phi1[4][4], const unsigned plo1[4][4],
                                         unsigned buf, unsigned hoff, unsigned vrow) {
#pragma unroll
    for (int dd = 0; dd < 4; dd++) {
        const unsigned aH = buf + oVH + hoff + swz(vrow + (unsigned)(dd * 32));
#pragma unroll
        for (int kb = 0; kb < 4; kb++) {
            unsigned bfr[4];
            ldsm_x4_t(bfr, aH + (unsigned)(kb * 2048));
            mma16816(oacc0[2 * dd],     phi0[kb], bfr);
            mma16816(oacc0[2 * dd + 1], phi0[kb], bfr + 2);
            mma16816(oacc1[2 * dd],     phi1[kb], bfr);
            mma16816(oacc1[2 * dd + 1], phi1[kb], bfr + 2);
            mma16816(oacc0[2 * dd],     plo0[kb], bfr);
            mma16816(oacc0[2 * dd + 1], plo0[kb], bfr + 2);
            mma16816(oacc1[2 * dd],     plo1[kb], bfr);
            mma16816(oacc1[2 * dd + 1], plo1[kb], bfr + 2);
        }
        const unsigned aL = buf + oVL + hoff + swz(vrow + (unsigned)(dd * 32));
#pragma unroll
        for (int kb = 0; kb < 4; kb++) {
            unsigned bfr[4];
            ldsm_x4_t(bfr, aL + (unsigned)(kb * 2048));
            mma16816(oacc0[2 * dd],     phi0[kb], bfr);
            mma16816(oacc0[2 * dd + 1], phi0[kb], bfr + 2);
            mma16816(oacc1[2 * dd],     phi1[kb], bfr);
            mma16816(oacc1[2 * dd + 1], phi1[kb], bfr + 2);
        }
    }
}

// ---------------- main attention kernel -------------------------------------
__global__ __launch_bounds__(NTHREADS, 1)
void attn_kernel(const float* __restrict__ q, const float* __restrict__ ctx) {
    extern __shared__ char smem[];
    const unsigned sbase = smem_u32(smem);
    const int tid = threadIdx.x;
    const int warp = tid >> 5, lane = tid & 31;
    const int g = lane >> 2, tq = lane & 3;
    const int ii = lane >> 3, jj = lane & 7;      // ldmatrix lane decomposition
    const int row0 = blockIdx.x * BT;
    const int split = blockIdx.y;
    const int m_base = split * MCHUNK;
    const int rgb = row0 + warp * 32;             // warp's 32-row block

    // hoisted swizzled sub-addresses (per-thread constants)
    const unsigned kbase0 = swz((unsigned)(jj * 128 + ii * 16));        // kbp=0
    const unsigned kbase1 = swz((unsigned)(jj * 128 + 64 + ii * 16));   // kbp=1
    const unsigned vrow   = (unsigned)(((ii & 1) * 8 + jj) * 128 + (ii >> 1) * 16);

    // ---- A fragments: Q (2 mb x 4 kb) and 0.5*ctx (2 mb x 2 kb), hi/lo -----
    unsigned qh[2][4][4], ql[2][4][4], ch[2][2][4], cl[2][2][4];
#pragma unroll
    for (int mb = 0; mb < 2; mb++) {
        const int rg = rgb + mb * 16 + g;
#pragma unroll
        for (int kb = 0; kb < 4; kb++) {
            int c0 = kb * 16 + 2 * tq;
            const float* q0 = q + (size_t)rg * D_;
            const float* q1 = q + (size_t)(rg + 8) * D_;
            float2 x00 = *(const float2*)(q0 + c0);
            float2 x10 = *(const float2*)(q1 + c0);
            float2 x01 = *(const float2*)(q0 + c0 + 8);
            float2 x11 = *(const float2*)(q1 + c0 + 8);
            pack_hl(x00.x, x00.y, qh[mb][kb][0], ql[mb][kb][0]);
            pack_hl(x10.x, x10.y, qh[mb][kb][1], ql[mb][kb][1]);
            pack_hl(x01.x, x01.y, qh[mb][kb][2], ql[mb][kb][2]);
            pack_hl(x11.x, x11.y, qh[mb][kb][3], ql[mb][kb][3]);
        }
#pragma unroll
        for (int kb = 0; kb < 2; kb++) {
            int c0 = kb * 16 + 2 * tq;
            const float* c0p = ctx + (size_t)rg * CD_;
            const float* c1p = ctx + (size_t)(rg + 8) * CD_;
            float2 x00 = *(const float2*)(c0p + c0);
            float2 x10 = *(const float2*)(c1p + c0);
            float2 x01 = *(const float2*)(c0p + c0 + 8);
            float2 x11 = *(const float2*)(c1p + c0 + 8);
            pack_hl(0.5f * x00.x, 0.5f * x00.y, ch[mb][kb][0], cl[mb][kb][0]);
            pack_hl(0.5f * x10.x, 0.5f * x10.y, ch[mb][kb][1], cl[mb][kb][1]);
            pack_hl(0.5f * x01.x, 0.5f * x01.y, ch[mb][kb][2], cl[mb][kb][2]);
            pack_hl(0.5f * x11.x, 0.5f * x11.y, ch[mb][kb][3], cl[mb][kb][3]);
        }
    }

    float oacc0[8][4] = {}, oacc1[8][4] = {};
    float dden[2][2] = {};

    stage_tile(m_base, sbase, tid);

    for (int t = 0; t < NTILES; t++) {
        CP_WAIT0();
        __syncthreads();
        if (t + 1 < NTILES)
            stage_tile(m_base + (t + 1) * MT, sbase + (unsigned)((t + 1) & 1) * BUFSZ, tid);

        const unsigned buf = sbase + (unsigned)(t & 1) * BUFSZ;
        const float* sBt = (const float*)(smem + (size_t)(t & 1) * BUFSZ + oBias);

#pragma unroll
        for (int h = 0; h < 2; h++) {
            const unsigned hoff = (unsigned)h * 8192u;
            float sacc0[8][4], sacc1[8][4];
            qk_half2(sacc0, sacc1, qh, ql, ch, cl, buf, hoff,
                     sBt + h * 64, tq, kbase0, kbase1);
            unsigned phi0[4][4], plo0[4][4], phi1[4][4], plo1[4][4];
            epi_half(sacc0, phi0, plo0, dden[0][0], dden[0][1]);
            epi_half(sacc1, phi1, plo1, dden[1][0], dden[1][1]);
            pv_half2(oacc0, oacc1, phi0, plo0, phi1, plo1, buf, hoff, vrow);
        }
    }

    // ---- row-sum reduce across quad lanes, write split partials ------------
#pragma unroll
    for (int mb = 0; mb < 2; mb++) {
        float d0 = dden[mb][0], d1 = dden[mb][1];
        d0 += __shfl_xor_sync(0xffffffffu, d0, 1);
        d0 += __shfl_xor_sync(0xffffffffu, d0, 2);
        d1 += __shfl_xor_sync(0xffffffffu, d1, 1);
        d1 += __shfl_xor_sync(0xffffffffu, d1, 2);
        const int rg = rgb + mb * 16 + g;
        if (tq == 0) {
            g_pden[(size_t)rg * S_ + split] = d0;
            g_pden[(size_t)(rg + 8) * S_ + split] = d1;
        }
        size_t base0 = ((size_t)rg * S_ + split) * D_;
        size_t base1 = ((size_t)(rg + 8) * S_ + split) * D_;
        const float (*oa)[4] = mb ? oacc1 : oacc0;
#pragma unroll
        for (int nd = 0; nd < 8; nd++) {
            *(float2*)(g_pout + base0 + nd * 8 + 2 * tq) = make_float2(oa[nd][0], oa[nd][1]);
            *(float2*)(g_pout + base1 + nd * 8 + 2 * tq) = make_float2(oa[nd][2], oa[nd][3]);
        }
    }
}

// ---------------- combine: normalize across splits --------------------------
__global__ void combine_kernel(float* __restrict__ out) {
    int b = blockIdx.x;
    int d = threadIdx.x;   // 64
    float num = 0.0f, den = 0.0f;
#pragma unroll
    for (int s = 0; s < S_; s++) {
        num += g_pout[((size_t)b * S_ + s) * D_ + d];
        den += g_pden[(size_t)b * S_ + s];
    }
    out[(size_t)b * D_ + d] = num / den;
}

// ---------------- launch -----------------------------------------------------
extern "C" void kernel_launch(void* const* d_in, const int* in_sizes, int n_in,
                              void* d_out, int out_size) {
    const float* q   = (const float*)d_in[0];
    const float* ctx = (const float*)d_in[1];
    const float* mk  = (const float*)d_in[2];
    const float* mv  = (const float*)d_in[3];
    const float* mc  = (const float*)d_in[4];
    const float* ts  = (const float*)d_in[5];
    const int*   us  = (const int*)d_in[6];
    float* out = (float*)d_out;

    cudaFuncSetAttribute(attn_kernel,
                         cudaFuncAttributeMaxDynamicSharedMemorySize, SMEM_TOTAL);

    prep_kernel<<<(M_ * D_ / 4) / 256, 256>>>(mk, mv, mc, ts, us);
    attn_kernel<<<dim3(B_ / BT, S_), NTHREADS, SMEM_TOTAL>>>(q, ctx);
    combine_kernel<<<B_, 64>>>(out);
}

// round 17
// speedup vs baseline: 1.8453x; 1.8453x over previous
#include <cuda_runtime.h>
#include <cuda_fp16.h>
#include <math.h>

#define B_   4096
#define M_   65536
#define D_   64
#define CD_  32
#define S_   32
#define MCHUNK (M_/S_)        // 2048 slots per CTA
#define MT    128             // slots per staged tile (2 x 64 compute halves)
#define NTILES (MCHUNK/MT)    // 16
#define BT    128             // batch rows per CTA (8 warps x 16)
#define NTHREADS 256

// smem buffer layout (byte offsets within one buffer); all tiles 1024-aligned
#define oKH   0u
#define oVH   16384u
#define oCH   32768u
#define oBias 49152u          // 128 floats
#define BUFSZ 50176u          // padded to 1024
#define SMEM_TOTAL (2u*BUFSZ) // 100352

// ---------------- device scratch (no cudaMalloc allowed) -------------------
__device__ __half g_kh[(size_t)M_*D_];
__device__ __half g_vh[(size_t)M_*D_];
__device__ __half g_ch[(size_t)M_*CD_];
__device__ float g_bias[M_];
__device__ float g_pout[(size_t)B_*S_*D_];
__device__ float g_pden[(size_t)B_*S_];

// ---------------- helpers ---------------------------------------------------
__device__ __forceinline__ unsigned smem_u32(const void* p) {
    unsigned a;
    asm("{ .reg .u64 t; cvta.to.shared.u64 t, %1; cvt.u32.u64 %0, t; }"
        : "=r"(a) : "l"(p));
    return a;
}
__device__ __forceinline__ unsigned swz(unsigned o) { return o ^ ((o >> 3) & 0x70); }

__device__ __forceinline__ void cp16(unsigned d, const void* s) {
    asm volatile("cp.async.cg.shared.global [%0], [%1], 16;" :: "r"(d), "l"(s));
}
#define CP_COMMIT() asm volatile("cp.async.commit_group;" ::: "memory")
#define CP_WAIT0()  asm volatile("cp.async.wait_group 0;" ::: "memory")

__device__ __forceinline__ void ldsm_x4(unsigned* r, unsigned a) {
    asm volatile("ldmatrix.sync.aligned.m8n8.x4.shared.b16 {%0,%1,%2,%3}, [%4];"
        : "=r"(r[0]), "=r"(r[1]), "=r"(r[2]), "=r"(r[3]) : "r"(a));
}
__device__ __forceinline__ void ldsm_x4_t(unsigned* r, unsigned a) {
    asm volatile("ldmatrix.sync.aligned.m8n8.x4.trans.shared.b16 {%0,%1,%2,%3}, [%4];"
        : "=r"(r[0]), "=r"(r[1]), "=r"(r[2]), "=r"(r[3]) : "r"(a));
}

// D(16x8,f32) += A(16x16,f16) * B(16x8,f16)
__device__ __forceinline__ void mma16816(float* c, const unsigned* a, const unsigned* b) {
    asm volatile("mma.sync.aligned.m16n8k16.row.col.f32.f16.f16.f32 "
        "{%0,%1,%2,%3}, {%4,%5,%6,%7}, {%8,%9}, {%0,%1,%2,%3};"
        : "+f"(c[0]), "+f"(c[1]), "+f"(c[2]), "+f"(c[3])
        : "r"(a[0]), "r"(a[1]), "r"(a[2]), "r"(a[3]), "r"(b[0]), "r"(b[1]));
}

// pack (a=low half, b=high half) into one f16x2 word
__device__ __forceinline__ unsigned pack2(float a, float b) {
    unsigned h;
    asm("cvt.rn.f16x2.f32 %0, %1, %2;" : "=r"(h) : "f"(b), "f"(a));
    return h;
}
// hi word + f16x2 residual word (x = hi + lo at fp16^2 accuracy)
__device__ __forceinline__ void pack_hl(float a, float b, unsigned& h, unsigned& l) {
    h = pack2(a, b);
    __half2 hh = *reinterpret_cast<__half2*>(&h);
    float2 hr = __half22float2(hh);
    l = pack2(a - hr.x, b - hr.y);
}

// ---------------- prep: fp16 casts + bias (4 elems/thread) ------------------
__global__ void prep_kernel(const float* __restrict__ mk,
                            const float* __restrict__ mv,
                            const float* __restrict__ mc,
                            const float* __restrict__ ts,
                            const int* __restrict__ used) {
    size_t i = (size_t)blockIdx.x * 256 + threadIdx.x;   // group of 4 elems
    if (i < (size_t)M_ * D_ / 4) {
        float4 x = ((const float4*)mk)[i];
        ((uint2*)g_kh)[i] = make_uint2(pack2(x.x, x.y), pack2(x.z, x.w));
        float4 y = ((const float4*)mv)[i];
        ((uint2*)g_vh)[i] = make_uint2(pack2(y.x, y.y), pack2(y.z, y.w));
    }
    if (i < (size_t)M_ * CD_ / 4) {
        float4 x = ((const float4*)mc)[i];
        ((uint2*)g_ch)[i] = make_uint2(pack2(x.x, x.y), pack2(x.z, x.w));
    }
    if (i < M_) {
        float b = -1e9f;
        if (used[i] != 0) b = 0.3f * expf(-0.1f * (1.0f - ts[i]));
        g_bias[i] = b;
    }
}

// ---------------- tile stage (cp.async, fixed-trip, shift-only math) --------
__device__ __forceinline__ void stage_tile(int m0, unsigned dst, int tid) {
#pragma unroll
    for (int i = 0; i < 4; i++) {      // K: 1024 cp16 (128 rows x 128B)
        int idx = tid + i * 256;
        int r = idx >> 3, c = idx & 7;
        cp16(dst + oKH + swz((unsigned)(r * 128 + c * 16)),
             (const char*)(g_kh + ((size_t)(m0 + r) << 6) + c * 8));
    }
#pragma unroll
    for (int i = 0; i < 4; i++) {      // V: 1024 cp16
        int idx = tid + i * 256;
        int r = idx >> 3, c = idx & 7;
        cp16(dst + oVH + swz((unsigned)(r * 128 + c * 16)),
             (const char*)(g_vh + ((size_t)(m0 + r) << 6) + c * 8));
    }
#pragma unroll
    for (int i = 0; i < 2; i++) {      // C: 512 cp16 (64B payload/row)
        int idx = tid + i * 256;
        int r = idx >> 2, c = idx & 3;
        cp16(dst + oCH + swz((unsigned)(r * 128 + c * 16)),
             (const char*)(g_ch + ((size_t)(m0 + r) << 5) + c * 8));
    }
    if (tid < 32)                      // bias: 128 floats
        cp16(dst + oBias + (unsigned)(tid * 16), (const char*)(g_bias + m0 + tid * 4));
    CP_COMMIT();
}

// ---------------- per-half building blocks (forceinlined) -------------------
struct Frags {
    unsigned qh[4][4], ql[4][4], ch[2][4], cl[2][4];
};

// QK 2-term: K-hi fragments feed qh AND ql (4 MMAs/ldsm); C-hi feeds ch+cl.
__device__ __forceinline__ void qk_half(float sacc[8][4], const Frags& f,
                                        unsigned buf, unsigned hoff,
                                        const float* sB, int tq,
                                        unsigned kbase0, unsigned kbase1) {
#pragma unroll
    for (int n = 0; n < 8; n++) {
        float2 b = *(const float2*)(sB + n * 8 + 2 * tq);
        sacc[n][0] = b.x; sacc[n][1] = b.y;
        sacc[n][2] = b.x; sacc[n][3] = b.y;
    }
#pragma unroll
    for (int kbp = 0; kbp < 2; kbp++) {
        const unsigned a0 = buf + oKH + hoff + (kbp ? kbase1 : kbase0);
#pragma unroll
        for (int n = 0; n < 8; n++) {
            unsigned bfr[4];
            ldsm_x4(bfr, a0 + (unsigned)(n * 1024));
            mma16816(sacc[n], f.qh[2 * kbp],     bfr);
            mma16816(sacc[n], f.qh[2 * kbp + 1], bfr + 2);
            mma16816(sacc[n], f.ql[2 * kbp],     bfr);
            mma16816(sacc[n], f.ql[2 * kbp + 1], bfr + 2);
        }
    }
    {
        const unsigned a0 = buf + oCH + hoff + kbase0;
#pragma unroll
        for (int n = 0; n < 8; n++) {
            unsigned bfr[4];
            ldsm_x4(bfr, a0 + (unsigned)(n * 1024));
            mma16816(sacc[n], f.ch[0], bfr);
            mma16816(sacc[n], f.ch[1], bfr + 2);
            mma16816(sacc[n], f.cl[0], bfr);
            mma16816(sacc[n], f.cl[1], bfr + 2);
        }
    }
}

__device__ __forceinline__ void epi_half(const float sacc[8][4],
                                         unsigned phi[4][4],
                                         float& dden0, float& dden1) {
#pragma unroll
    for (int n = 0; n < 8; n++) {
        float p0 = __expf(sacc[n][0]);
        float p1 = __expf(sacc[n][1]);
        float p2 = __expf(sacc[n][2]);
        float p3 = __expf(sacc[n][3]);
        dden0 += p0 + p1;
        dden1 += p2 + p3;
        int kb = n >> 1, e = (n & 1) * 2;
        phi[kb][e]     = pack2(p0, p1);
        phi[kb][e + 1] = pack2(p2, p3);
    }
}

// PV 1-term: each V fragment feeds phi only (2 MMAs/ldsm)
__device__ __forceinline__ void pv_half(float oacc[8][4],
                                        const unsigned phi[4][4],
                                        unsigned buf, unsigned hoff, unsigned vrow) {
#pragma unroll
    for (int dd = 0; dd < 4; dd++) {
        const unsigned aH = buf + oVH + hoff + swz(vrow + (unsigned)(dd * 32));
#pragma unroll
        for (int kb = 0; kb < 4; kb++) {
            unsigned bfr[4];
            ldsm_x4_t(bfr, aH + (unsigned)(kb * 2048));
            mma16816(oacc[2 * dd],     phi[kb], bfr);
            mma16816(oacc[2 * dd + 1], phi[kb], bfr + 2);
        }
    }
}

// ---------------- main attention kernel -------------------------------------
__global__ __launch_bounds__(NTHREADS, 1)
void attn_kernel(const float* __restrict__ q, const float* __restrict__ ctx) {
    extern __shared__ char smem[];
    const unsigned sbase = smem_u32(smem);
    const int tid = threadIdx.x;
    const int warp = tid >> 5, lane = tid & 31;
    const int g = lane >> 2, tq = lane & 3;
    const int ii = lane >> 3, jj = lane & 7;      // ldmatrix lane decomposition
    const int row0 = blockIdx.x * BT;
    const int split = blockIdx.y;
    const int m_base = split * MCHUNK;
    const int rg = row0 + warp * 16 + g;          // this thread's rows: rg, rg+8

    // hoisted swizzled sub-addresses (per-thread constants)
    const unsigned kbase0 = swz((unsigned)(jj * 128 + ii * 16));        // kbp=0
    const unsigned kbase1 = swz((unsigned)(jj * 128 + 64 + ii * 16));   // kbp=1
    const unsigned vrow   = (unsigned)(((ii & 1) * 8 + jj) * 128 + (ii >> 1) * 16);

    // ---- A fragments: Q (4 kblocks) and 0.5*ctx (2 kblocks), fp16 hi/lo ----
    Frags f;
#pragma unroll
    for (int kb = 0; kb < 4; kb++) {
        int c0 = kb * 16 + 2 * tq;
        const float* q0 = q + (size_t)rg * D_;
        const float* q1 = q + (size_t)(rg + 8) * D_;
        float2 x00 = *(const float2*)(q0 + c0);
        float2 x10 = *(const float2*)(q1 + c0);
        float2 x01 = *(const float2*)(q0 + c0 + 8);
        float2 x11 = *(const float2*)(q1 + c0 + 8);
        pack_hl(x00.x, x00.y, f.qh[kb][0], f.ql[kb][0]);
        pack_hl(x10.x, x10.y, f.qh[kb][1], f.ql[kb][1]);
        pack_hl(x01.x, x01.y, f.qh[kb][2], f.ql[kb][2]);
        pack_hl(x11.x, x11.y, f.qh[kb][3], f.ql[kb][3]);
    }
#pragma unroll
    for (int kb = 0; kb < 2; kb++) {
        int c0 = kb * 16 + 2 * tq;
        const float* c0p = ctx + (size_t)rg * CD_;
        const float* c1p = ctx + (size_t)(rg + 8) * CD_;
        float2 x00 = *(const float2*)(c0p + c0);
        float2 x10 = *(const float2*)(c1p + c0);
        float2 x01 = *(const float2*)(c0p + c0 + 8);
        float2 x11 = *(const float2*)(c1p + c0 + 8);
        pack_hl(0.5f * x00.x, 0.5f * x00.y, f.ch[kb][0], f.cl[kb][0]);
        pack_hl(0.5f * x10.x, 0.5f * x10.y, f.ch[kb][1], f.cl[kb][1]);
        pack_hl(0.5f * x01.x, 0.5f * x01.y, f.ch[kb][2], f.cl[kb][2]);
        pack_hl(0.5f * x11.x, 0.5f * x11.y, f.ch[kb][3], f.cl[kb][3]);
    }

    float oacc[8][4] = {};
    float dden0 = 0.0f, dden1 = 0.0f;

    stage_tile(m_base, sbase, tid);

    for (int t = 0; t < NTILES; t++) {
        CP_WAIT0();
        __syncthreads();
        if (t + 1 < NTILES)
            stage_tile(m_base + (t + 1) * MT, sbase + (unsigned)((t + 1) & 1) * BUFSZ, tid);

        const unsigned buf = sbase + (unsigned)(t & 1) * BUFSZ;
        const float* sBt = (const float*)(smem + (size_t)(t & 1) * BUFSZ + oBias);

        // order B (best measured): QK both halves, then epi+PV per half
        float sacc[2][8][4];
#pragma unroll
        for (int h = 0; h < 2; h++)
            qk_half(sacc[h], f, buf, (unsigned)h * 8192u, sBt + h * 64,
                    tq, kbase0, kbase1);
#pragma unroll
        for (int h = 0; h < 2; h++) {
            unsigned phi[4][4];
            epi_half(sacc[h], phi, dden0, dden1);
            pv_half(oacc, phi, buf, (unsigned)h * 8192u, vrow);
        }
    }

    // ---- row-sum reduce across quad lanes, write split partials ------------
    dden0 += __shfl_xor_sync(0xffffffffu, dden0, 1);
    dden0 += __shfl_xor_sync(0xffffffffu, dden0, 2);
    dden1 += __shfl_xor_sync(0xffffffffu, dden1, 1);
    dden1 += __shfl_xor_sync(0xffffffffu, dden1, 2);
    if (tq == 0) {
        g_pden[(size_t)rg * S_ + split] = dden0;
        g_pden[(size_t)(rg + 8) * S_ + split] = dden1;
    }
    size_t base0 = ((size_t)rg * S_ + split) * D_;
    size_t base1 = ((size_t)(rg + 8) * S_ + split) * D_;
#pragma unroll
    for (int nd = 0; nd < 8; nd++) {
        *(float2*)(g_pout + base0 + nd * 8 + 2 * tq) = make_float2(oacc[nd][0], oacc[nd][1]);
        *(float2*)(g_pout + base1 + nd * 8 + 2 * tq) = make_float2(oacc[nd][2], oacc[nd][3]);
    }
}

// ---------------- combine: normalize across splits --------------------------
__global__ void combine_kernel(float* __restrict__ out) {
    int b = blockIdx.x;
    int d = threadIdx.x;   // 64
    float num = 0.0f, den = 0.0f;
#pragma unroll
    for (int s = 0; s < S_; s++) {
        num += g_pout[((size_t)b * S_ + s) * D_ + d];
        den += g_pden[(size_t)b * S_ + s];
    }
    out[(size_t)b * D_ + d] = num / den;
}

// ---------------- launch -----------------------------------------------------
extern "C" void kernel_launch(void* const* d_in, const int* in_sizes, int n_in,
                              void* d_out, int out_size) {
    const float* q   = (const float*)d_in[0];
    const float* ctx = (const float*)d_in[1];
    const float* mk  = (const float*)d_in[2];
    const float* mv  = (const float*)d_in[3];
    const float* mc  = (const float*)d_in[4];
    const float* ts  = (const float*)d_in[5];
    const int*   us  = (const int*)d_in[6];
    float* out = (float*)d_out;

    cudaFuncSetAttribute(attn_kernel,
                         cudaFuncAttributeMaxDynamicSharedMemorySize, SMEM_TOTAL);

    prep_kernel<<<(M_ * D_ / 4) / 256, 256>>>(mk, mv, mc, ts, us);
    attn_kernel<<<dim3(B_ / BT, S_), NTHREADS, SMEM_TOTAL>>>(q, ctx);
    combine_kernel<<<B_, 64>>>(out);
}